// round 1
// baseline (speedup 1.0000x reference)
#include <cuda_runtime.h>
#include <math.h>
#include <stdint.h>

#define N_NODES 100000
#define N_EDGES 1600000
#define DIM 128
#define OUT_DIM 47

// ---------------- scratch (static device allocations) ----------------
__device__ float d_G[(size_t)N_NODES * DIM];   // h @ Wl  (gather source)
__device__ float d_Z[(size_t)N_NODES * DIM];   // h @ Wr + b (self term)
__device__ float d_hA[(size_t)N_NODES * DIM];  // hidden after layer 0
__device__ float d_hB[(size_t)N_NODES * DIM];  // hidden after layer 1
__device__ float d_invd[N_NODES];
__device__ int   d_count[N_NODES];
__device__ int   d_off[N_NODES + 1];
__device__ int   d_cursor[N_NODES];
__device__ int   d_esrc[N_EDGES];

// ---------------- CSR build ----------------
__global__ void count_kernel(const int* __restrict__ dst) {
    int e = blockIdx.x * blockDim.x + threadIdx.x;
    if (e < N_EDGES) atomicAdd(&d_count[dst[e]], 1);
}

__global__ void scan_kernel() {
    __shared__ int ssum[1024];
    const int t = threadIdx.x;
    const int CH = (N_NODES + 1023) / 1024;  // 98
    int lo = t * CH;
    int hi = lo + CH; if (hi > N_NODES) hi = N_NODES;
    if (lo > N_NODES) lo = N_NODES;
    int s = 0;
    for (int i = lo; i < hi; i++) s += d_count[i];
    ssum[t] = s;
    __syncthreads();
    // inclusive Hillis-Steele scan over 1024 partials
    for (int o = 1; o < 1024; o <<= 1) {
        int v = (t >= o) ? ssum[t - o] : 0;
        __syncthreads();
        ssum[t] += v;
        __syncthreads();
    }
    int run = (t > 0) ? ssum[t - 1] : 0;
    for (int i = lo; i < hi; i++) {
        int ci = d_count[i];
        d_off[i] = run;
        d_cursor[i] = run;
        d_invd[i] = (ci > 0) ? (1.0f / (float)ci) : 0.0f;
        run += ci;
    }
    if (t == 1023) d_off[N_NODES] = ssum[1023];
}

__global__ void scatter_kernel(const int* __restrict__ src, const int* __restrict__ dst) {
    int e = blockIdx.x * blockDim.x + threadIdx.x;
    if (e < N_EDGES) {
        int d = dst[e];
        int p = atomicAdd(&d_cursor[d], 1);
        d_esrc[p] = src[e];
    }
}

// ---------------- GEMM: C[M x Nout] = A[M x 128] @ B[128 x Nout] (+bias) --------------
// 128x128 block tile, K=128 fully resident in smem, 8x8 microtile per thread,
// accumulators in packed f32x2 (FFMA2 path: 2x fp32 throughput on sm_103a).
#define GEMM_SMEM_BYTES ((128 * 129 + 128 * 128) * 4)

__global__ __launch_bounds__(256, 1)
void gemm_k128(const float* __restrict__ A, const float* __restrict__ B,
               const float* __restrict__ bias, float* __restrict__ C,
               int M, int Nout) {
    extern __shared__ float smem[];
    float(*As)[129] = (float(*)[129])smem;                 // As[m][k], pad 129 -> conflict-free column reads
    float(*Bs)[128] = (float(*)[128])(smem + 128 * 129);   // Bs[k][n]

    const int t = threadIdx.x;
    const int m0 = blockIdx.x * 128;

    // Load A tile (128 rows x 128 cols), coalesced float4
#pragma unroll
    for (int i = 0; i < 16; i++) {
        int f = i * 256 + t;          // 0..4095 float4s
        int row = f >> 5;
        int c4 = f & 31;
        float4 v = make_float4(0.f, 0.f, 0.f, 0.f);
        if (m0 + row < M)
            v = reinterpret_cast<const float4*>(A + (size_t)(m0 + row) * 128)[c4];
        As[row][c4 * 4 + 0] = v.x;
        As[row][c4 * 4 + 1] = v.y;
        As[row][c4 * 4 + 2] = v.z;
        As[row][c4 * 4 + 3] = v.w;
    }
    // Load B (128 x Nout) into Bs[k][n], zero-pad n >= Nout
#pragma unroll
    for (int i = 0; i < 64; i++) {
        int f = i * 256 + t;          // 0..16383
        int k = f >> 7;
        int n = f & 127;
        Bs[k][n] = (n < Nout) ? B[k * Nout + n] : 0.0f;
    }
    __syncthreads();

    const int tx = t & 15, ty = t >> 4;
    const int row0 = ty * 8, col0 = tx * 8;

    unsigned long long c2[8][4];
#pragma unroll
    for (int i = 0; i < 8; i++)
#pragma unroll
        for (int j = 0; j < 4; j++) c2[i][j] = 0ull;

#pragma unroll 4
    for (int k = 0; k < 128; k++) {
        unsigned long long a2[8];
#pragma unroll
        for (int i = 0; i < 8; i++) {
            float a = As[row0 + i][k];
            asm("mov.b64 %0, {%1, %1};" : "=l"(a2[i]) : "f"(a));
        }
        unsigned long long b2[4];
        {
            const ulonglong2* bp = reinterpret_cast<const ulonglong2*>(&Bs[k][col0]);
            ulonglong2 u0 = bp[0];
            ulonglong2 u1 = bp[1];
            b2[0] = u0.x; b2[1] = u0.y; b2[2] = u1.x; b2[3] = u1.y;
        }
#pragma unroll
        for (int i = 0; i < 8; i++)
#pragma unroll
            for (int j = 0; j < 4; j++)
                asm("fma.rn.f32x2 %0, %1, %2, %0;"
                    : "+l"(c2[i][j]) : "l"(a2[i]), "l"(b2[j]));
    }

    // Store
#pragma unroll
    for (int i = 0; i < 8; i++) {
        int r = m0 + row0 + i;
        if (r >= M) continue;
        float* crow = C + (size_t)r * Nout;
#pragma unroll
        for (int j = 0; j < 4; j++) {
            float lo, hi;
            asm("mov.b64 {%0, %1}, %2;" : "=f"(lo), "=f"(hi) : "l"(c2[i][j]));
            int n = col0 + j * 2;
            if (n < Nout)     crow[n]     = lo + (bias ? bias[n] : 0.0f);
            if (n + 1 < Nout) crow[n + 1] = hi + (bias ? bias[n + 1] : 0.0f);
        }
    }
}

// ---------------- aggregation (128-wide layers): out = relu?(Z + invd * sum G[src]) ----
__global__ void agg128(const float* __restrict__ G, const float* __restrict__ Z,
                       float* __restrict__ out, int do_relu) {
    const int v = blockIdx.x;
    const int c = threadIdx.x;  // 128
    __shared__ int sidx[128];
    const int e0 = d_off[v], e1 = d_off[v + 1];
    float a0 = 0.f, a1 = 0.f, a2 = 0.f, a3 = 0.f;
    for (int base = e0; base < e1; base += 128) {
        int n = e1 - base; if (n > 128) n = 128;
        __syncthreads();
        if (c < n) sidx[c] = d_esrc[base + c];
        __syncthreads();
        int i = 0;
        for (; i + 4 <= n; i += 4) {
            const float* g0 = G + (size_t)sidx[i + 0] * 128;
            const float* g1 = G + (size_t)sidx[i + 1] * 128;
            const float* g2 = G + (size_t)sidx[i + 2] * 128;
            const float* g3 = G + (size_t)sidx[i + 3] * 128;
            a0 += __ldg(&g0[c]);
            a1 += __ldg(&g1[c]);
            a2 += __ldg(&g2[c]);
            a3 += __ldg(&g3[c]);
        }
        for (; i < n; i++) a0 += __ldg(&G[(size_t)sidx[i] * 128 + c]);
    }
    float r = Z[(size_t)v * 128 + c] + d_invd[v] * ((a0 + a1) + (a2 + a3));
    if (do_relu) r = fmaxf(r, 0.0f);
    out[(size_t)v * 128 + c] = r;
}

// ---------------- layer-2 aggregation + log_softmax (47-wide) ----------------
__global__ void agg_lsm47(const float* __restrict__ G, const float* __restrict__ Z,
                          float* __restrict__ out) {
    const int v = blockIdx.x;
    const int c = threadIdx.x;  // 64 threads, 2 warps
    __shared__ int sidx[128];
    __shared__ float wred[2];
    const int e0 = d_off[v], e1 = d_off[v + 1];
    float acc = 0.f;
    for (int base = e0; base < e1; base += 128) {
        int n = e1 - base; if (n > 128) n = 128;
        __syncthreads();
        if (c < n) sidx[c] = d_esrc[base + c];
        if (c + 64 < n) sidx[c + 64] = d_esrc[base + c + 64];
        __syncthreads();
        if (c < OUT_DIM) {
            for (int i = 0; i < n; i++)
                acc += __ldg(&G[(size_t)sidx[i] * OUT_DIM + c]);
        }
    }
    float val = (c < OUT_DIM) ? (Z[(size_t)v * OUT_DIM + c] + d_invd[v] * acc) : -1e30f;

    // block max over 64 threads
    float m = val;
#pragma unroll
    for (int o = 16; o > 0; o >>= 1) m = fmaxf(m, __shfl_xor_sync(0xFFFFFFFFu, m, o));
    if ((c & 31) == 0) wred[c >> 5] = m;
    __syncthreads();
    m = fmaxf(wred[0], wred[1]);
    __syncthreads();

    float ex = (c < OUT_DIM) ? expf(val - m) : 0.0f;
    float s = ex;
#pragma unroll
    for (int o = 16; o > 0; o >>= 1) s += __shfl_xor_sync(0xFFFFFFFFu, s, o);
    if ((c & 31) == 0) wred[c >> 5] = s;
    __syncthreads();
    float total = wred[0] + wred[1];

    if (c < OUT_DIM) out[(size_t)v * OUT_DIM + c] = val - m - logf(total);
}

// ---------------- launch ----------------
extern "C" void kernel_launch(void* const* d_in, const int* in_sizes, int n_in,
                              void* d_out, int out_size) {
    const float* x   = (const float*)d_in[0];
    const int*   src = (const int*)d_in[1];
    const int*   dst = (const int*)d_in[2];
    const float* Wl0 = (const float*)d_in[3];
    const float* bl0 = (const float*)d_in[4];
    const float* Wr0 = (const float*)d_in[5];
    const float* Wl1 = (const float*)d_in[6];
    const float* bl1 = (const float*)d_in[7];
    const float* Wr1 = (const float*)d_in[8];
    const float* Wl2 = (const float*)d_in[9];
    const float* bl2 = (const float*)d_in[10];
    const float* Wr2 = (const float*)d_in[11];
    float* out = (float*)d_out;

    void *pG, *pZ, *pA, *pB, *pCnt;
    cudaGetSymbolAddress(&pG, d_G);
    cudaGetSymbolAddress(&pZ, d_Z);
    cudaGetSymbolAddress(&pA, d_hA);
    cudaGetSymbolAddress(&pB, d_hB);
    cudaGetSymbolAddress(&pCnt, d_count);
    float* G  = (float*)pG;
    float* Z  = (float*)pZ;
    float* hA = (float*)pA;
    float* hB = (float*)pB;

    cudaFuncSetAttribute(gemm_k128, cudaFuncAttributeMaxDynamicSharedMemorySize,
                         GEMM_SMEM_BYTES);

    // CSR build
    cudaMemsetAsync(pCnt, 0, N_NODES * sizeof(int));
    count_kernel<<<(N_EDGES + 255) / 256, 256>>>(dst);
    scan_kernel<<<1, 1024>>>();
    scatter_kernel<<<(N_EDGES + 255) / 256, 256>>>(src, dst);

    const int gemm_grid = (N_NODES + 127) / 128;

    // Layer 0
    gemm_k128<<<gemm_grid, 256, GEMM_SMEM_BYTES>>>(x, Wl0, nullptr, G, N_NODES, DIM);
    gemm_k128<<<gemm_grid, 256, GEMM_SMEM_BYTES>>>(x, Wr0, bl0,     Z, N_NODES, DIM);
    agg128<<<N_NODES, 128>>>(G, Z, hA, 1);

    // Layer 1
    gemm_k128<<<gemm_grid, 256, GEMM_SMEM_BYTES>>>(hA, Wl1, nullptr, G, N_NODES, DIM);
    gemm_k128<<<gemm_grid, 256, GEMM_SMEM_BYTES>>>(hA, Wr1, bl1,     Z, N_NODES, DIM);
    agg128<<<N_NODES, 128>>>(G, Z, hB, 1);

    // Layer 2 (width 47) + log_softmax
    gemm_k128<<<gemm_grid, 256, GEMM_SMEM_BYTES>>>(hB, Wl2, nullptr, G, N_NODES, OUT_DIM);
    gemm_k128<<<gemm_grid, 256, GEMM_SMEM_BYTES>>>(hB, Wr2, bl2,     Z, N_NODES, OUT_DIM);
    agg_lsm47<<<N_NODES, 64>>>(G, Z, out);
}

// round 2
// speedup vs baseline: 1.0683x; 1.0683x over previous
#include <cuda_runtime.h>
#include <math.h>
#include <stdint.h>

#define N_NODES 100000
#define N_EDGES 1600000
#define DIM 128
#define OUT_DIM 47
#define KC 32
#define AP 34   // As row pad (floats): rows 8 apart differ by 16 banks -> conflict-free

// ---------------- scratch ----------------
__device__ float d_G[(size_t)N_NODES * DIM];
__device__ float d_Z[(size_t)N_NODES * DIM];
__device__ float d_hA[(size_t)N_NODES * DIM];
__device__ float d_hB[(size_t)N_NODES * DIM];
__device__ float d_invd[N_NODES];
__device__ int   d_count[N_NODES];
__device__ int   d_off[N_NODES + 1];
__device__ int   d_cursor[N_NODES];
__device__ int   d_esrc[N_EDGES];

// ---------------- CSR build ----------------
__global__ void count_kernel(const int* __restrict__ dst) {
    int e = blockIdx.x * blockDim.x + threadIdx.x;
    if (e < N_EDGES) atomicAdd(&d_count[dst[e]], 1);
}

__global__ void scan_kernel() {
    __shared__ int ssum[1024];
    const int t = threadIdx.x;
    const int CH = (N_NODES + 1023) / 1024;
    int lo = t * CH;
    int hi = lo + CH; if (hi > N_NODES) hi = N_NODES;
    if (lo > N_NODES) lo = N_NODES;
    int s = 0;
    for (int i = lo; i < hi; i++) s += d_count[i];
    ssum[t] = s;
    __syncthreads();
    for (int o = 1; o < 1024; o <<= 1) {
        int v = (t >= o) ? ssum[t - o] : 0;
        __syncthreads();
        ssum[t] += v;
        __syncthreads();
    }
    int run = (t > 0) ? ssum[t - 1] : 0;
    for (int i = lo; i < hi; i++) {
        int ci = d_count[i];
        d_off[i] = run;
        d_cursor[i] = run;
        d_invd[i] = (ci > 0) ? (1.0f / (float)ci) : 0.0f;
        run += ci;
    }
    if (t == 1023) d_off[N_NODES] = ssum[1023];
}

__global__ void scatter_kernel(const int* __restrict__ src, const int* __restrict__ dst) {
    int e = blockIdx.x * blockDim.x + threadIdx.x;
    if (e < N_EDGES) {
        int d = dst[e];
        int p = atomicAdd(&d_cursor[d], 1);
        d_esrc[p] = src[e];
    }
}

// ---------------- helpers ----------------
__device__ __forceinline__ unsigned long long dup2(float a) {
    unsigned long long r;
    asm("mov.b64 %0, {%1, %1};" : "=l"(r) : "f"(a));
    return r;
}
__device__ __forceinline__ void ffma2(unsigned long long& c, unsigned long long a,
                                      unsigned long long b) {
    asm("fma.rn.f32x2 %0, %1, %2, %0;" : "+l"(c) : "l"(a), "l"(b));
}
__device__ __forceinline__ void unpk(unsigned long long c, float& lo, float& hi) {
    asm("mov.b64 {%0, %1}, %2;" : "=f"(lo), "=f"(hi) : "l"(c));
}

// ---------------- GEMM Nout=128: C = A[Mx128] @ B[128x128] (+bias) ----------------
__global__ __launch_bounds__(256, 2)
void gemm_n128(const float* __restrict__ A, const float* __restrict__ B,
               const float* __restrict__ bias, float* __restrict__ C, int M) {
    __shared__ float As[128 * AP];
    __shared__ float Bs[KC * 128];
    const int t = threadIdx.x;
    const int m0 = blockIdx.x * 128;
    const int tx = t & 15, ty = t >> 4;
    const int row0 = ty * 8, col0 = tx * 8;

    unsigned long long c2[8][4];
#pragma unroll
    for (int i = 0; i < 8; i++)
#pragma unroll
        for (int j = 0; j < 4; j++) c2[i][j] = 0ull;

    for (int k0 = 0; k0 < 128; k0 += KC) {
        __syncthreads();
        // A chunk: 128 rows x 32 k  (1024 float4, 4/thread), coalesced
#pragma unroll
        for (int i = 0; i < 4; i++) {
            int f = i * 256 + t;
            int row = f >> 3;
            int c4 = (f & 7) * 4;
            float4 v = make_float4(0.f, 0.f, 0.f, 0.f);
            if (m0 + row < M)
                v = *(const float4*)(A + (size_t)(m0 + row) * 128 + k0 + c4);
            // AP=34 -> row base only 8B aligned; store as two float2
            float* p = &As[row * AP + c4];
            *(float2*)(p)     = make_float2(v.x, v.y);
            *(float2*)(p + 2) = make_float2(v.z, v.w);
        }
        // B chunk: 32 x 128 (1024 float4, 4/thread)
#pragma unroll
        for (int i = 0; i < 4; i++) {
            int f = i * 256 + t;
            int row = f >> 5;
            int c4 = (f & 31) * 4;
            float4 v = *(const float4*)(B + (size_t)(k0 + row) * 128 + c4);
            *(float4*)&Bs[row * 128 + c4] = v;
        }
        __syncthreads();

#pragma unroll
        for (int k = 0; k < KC; k += 2) {
            float2 a01[8];
#pragma unroll
            for (int i = 0; i < 8; i++)
                a01[i] = *(const float2*)&As[(row0 + i) * AP + k];
#pragma unroll
            for (int u = 0; u < 2; u++) {
                ulonglong2 b0 = *(const ulonglong2*)&Bs[(k + u) * 128 + col0];
                ulonglong2 b1 = *(const ulonglong2*)&Bs[(k + u) * 128 + col0 + 4];
#pragma unroll
                for (int i = 0; i < 8; i++) {
                    unsigned long long a2 = dup2(u ? a01[i].y : a01[i].x);
                    ffma2(c2[i][0], a2, b0.x);
                    ffma2(c2[i][1], a2, b0.y);
                    ffma2(c2[i][2], a2, b1.x);
                    ffma2(c2[i][3], a2, b1.y);
                }
            }
        }
    }

    float bv[8];
#pragma unroll
    for (int j = 0; j < 8; j++) bv[j] = bias ? bias[col0 + j] : 0.0f;

#pragma unroll
    for (int i = 0; i < 8; i++) {
        int r = m0 + row0 + i;
        if (r >= M) continue;
        float o[8];
#pragma unroll
        for (int j = 0; j < 4; j++) unpk(c2[i][j], o[2 * j], o[2 * j + 1]);
#pragma unroll
        for (int j = 0; j < 8; j++) o[j] += bv[j];
        float* crow = C + (size_t)r * 128 + col0;
        *(float4*)(crow)     = make_float4(o[0], o[1], o[2], o[3]);
        *(float4*)(crow + 4) = make_float4(o[4], o[5], o[6], o[7]);
    }
}

// ---------------- GEMM Nout=47 (TN=64 tile): C = A[Mx128] @ B[128x47] (+bias) --------
__global__ __launch_bounds__(256, 2)
void gemm_n47(const float* __restrict__ A, const float* __restrict__ B,
              const float* __restrict__ bias, float* __restrict__ C, int M) {
    __shared__ float As[128 * AP];
    __shared__ float Bs[KC * 64];
    const int t = threadIdx.x;
    const int m0 = blockIdx.x * 128;
    const int tx = t & 7, ty = t >> 3;     // 8 x 32
    const int row0 = ty * 4, col0 = tx * 8;

    unsigned long long c2[4][4];
#pragma unroll
    for (int i = 0; i < 4; i++)
#pragma unroll
        for (int j = 0; j < 4; j++) c2[i][j] = 0ull;

    for (int k0 = 0; k0 < 128; k0 += KC) {
        __syncthreads();
#pragma unroll
        for (int i = 0; i < 4; i++) {
            int f = i * 256 + t;
            int row = f >> 3;
            int c4 = (f & 7) * 4;
            float4 v = make_float4(0.f, 0.f, 0.f, 0.f);
            if (m0 + row < M)
                v = *(const float4*)(A + (size_t)(m0 + row) * 128 + k0 + c4);
            float* p = &As[row * AP + c4];
            *(float2*)(p)     = make_float2(v.x, v.y);
            *(float2*)(p + 2) = make_float2(v.z, v.w);
        }
        // B chunk 32 x 64 (zero-pad cols >= 47), scalar loads, 8/thread
#pragma unroll
        for (int i = 0; i < 8; i++) {
            int f = i * 256 + t;
            int row = f >> 6;
            int n = f & 63;
            Bs[row * 64 + n] = (n < OUT_DIM) ? B[(size_t)(k0 + row) * OUT_DIM + n] : 0.0f;
        }
        __syncthreads();

#pragma unroll
        for (int k = 0; k < KC; k += 2) {
            float2 a01[4];
#pragma unroll
            for (int i = 0; i < 4; i++)
                a01[i] = *(const float2*)&As[(row0 + i) * AP + k];
#pragma unroll
            for (int u = 0; u < 2; u++) {
                ulonglong2 b0 = *(const ulonglong2*)&Bs[(k + u) * 64 + col0];
                ulonglong2 b1 = *(const ulonglong2*)&Bs[(k + u) * 64 + col0 + 4];
#pragma unroll
                for (int i = 0; i < 4; i++) {
                    unsigned long long a2 = dup2(u ? a01[i].y : a01[i].x);
                    ffma2(c2[i][0], a2, b0.x);
                    ffma2(c2[i][1], a2, b0.y);
                    ffma2(c2[i][2], a2, b1.x);
                    ffma2(c2[i][3], a2, b1.y);
                }
            }
        }
    }

#pragma unroll
    for (int i = 0; i < 4; i++) {
        int r = m0 + row0 + i;
        if (r >= M) continue;
        float* crow = C + (size_t)r * OUT_DIM;
#pragma unroll
        for (int j = 0; j < 4; j++) {
            float lo, hi;
            unpk(c2[i][j], lo, hi);
            int n = col0 + 2 * j;
            if (n < OUT_DIM)     crow[n]     = lo + (bias ? bias[n] : 0.0f);
            if (n + 1 < OUT_DIM) crow[n + 1] = hi + (bias ? bias[n + 1] : 0.0f);
        }
    }
}

// ---------------- aggregation, warp per node (128 cols, float4/lane) ----------------
__global__ void agg128_warp(const float* __restrict__ G, const float* __restrict__ Z,
                            float* __restrict__ out, int do_relu) {
    int w = (blockIdx.x * blockDim.x + threadIdx.x) >> 5;
    int lane = threadIdx.x & 31;
    if (w >= N_NODES) return;
    const int e0 = d_off[w], e1 = d_off[w + 1];
    const float4* Gv = (const float4*)G;
    float4 a0 = make_float4(0.f, 0.f, 0.f, 0.f);
    float4 a1 = make_float4(0.f, 0.f, 0.f, 0.f);
    int i = e0;
    for (; i + 2 <= e1; i += 2) {
        int s0 = d_esrc[i], s1 = d_esrc[i + 1];
        float4 r0 = __ldg(&Gv[(size_t)s0 * 32 + lane]);
        float4 r1 = __ldg(&Gv[(size_t)s1 * 32 + lane]);
        a0.x += r0.x; a0.y += r0.y; a0.z += r0.z; a0.w += r0.w;
        a1.x += r1.x; a1.y += r1.y; a1.z += r1.z; a1.w += r1.w;
    }
    if (i < e1) {
        float4 r0 = __ldg(&Gv[(size_t)d_esrc[i] * 32 + lane]);
        a0.x += r0.x; a0.y += r0.y; a0.z += r0.z; a0.w += r0.w;
    }
    float inv = d_invd[w];
    float4 z = __ldg(&((const float4*)Z)[(size_t)w * 32 + lane]);
    float4 o;
    o.x = z.x + inv * (a0.x + a1.x);
    o.y = z.y + inv * (a0.y + a1.y);
    o.z = z.z + inv * (a0.z + a1.z);
    o.w = z.w + inv * (a0.w + a1.w);
    if (do_relu) {
        o.x = fmaxf(o.x, 0.f); o.y = fmaxf(o.y, 0.f);
        o.z = fmaxf(o.z, 0.f); o.w = fmaxf(o.w, 0.f);
    }
    ((float4*)out)[(size_t)w * 32 + lane] = o;
}

// ---------------- layer-2 agg + log_softmax, warp per node (47 cols) ----------------
__global__ void agg_lsm47_warp(const float* __restrict__ G, const float* __restrict__ Z,
                               float* __restrict__ out) {
    int v = (blockIdx.x * blockDim.x + threadIdx.x) >> 5;
    int lane = threadIdx.x & 31;
    if (v >= N_NODES) return;
    const int e0 = d_off[v], e1 = d_off[v + 1];
    const int c1 = 32 + lane;
    const bool has1 = c1 < OUT_DIM;

    float a0 = 0.f, a1 = 0.f, b0 = 0.f, b1 = 0.f;
    int i = e0;
    for (; i + 2 <= e1; i += 2) {
        const float* g = G + (size_t)d_esrc[i] * OUT_DIM;
        const float* h = G + (size_t)d_esrc[i + 1] * OUT_DIM;
        a0 += __ldg(&g[lane]);
        b0 += __ldg(&h[lane]);
        if (has1) {
            a1 += __ldg(&g[c1]);
            b1 += __ldg(&h[c1]);
        }
    }
    if (i < e1) {
        const float* g = G + (size_t)d_esrc[i] * OUT_DIM;
        a0 += __ldg(&g[lane]);
        if (has1) a1 += __ldg(&g[c1]);
    }
    a0 += b0; a1 += b1;

    float inv = d_invd[v];
    const float* z = Z + (size_t)v * OUT_DIM;
    float v0 = z[lane] + inv * a0;
    float v1 = has1 ? (z[c1] + inv * a1) : -INFINITY;

    float m = fmaxf(v0, v1);
#pragma unroll
    for (int o = 16; o > 0; o >>= 1) m = fmaxf(m, __shfl_xor_sync(0xFFFFFFFFu, m, o));
    float s = expf(v0 - m) + (has1 ? expf(v1 - m) : 0.f);
#pragma unroll
    for (int o = 16; o > 0; o >>= 1) s += __shfl_xor_sync(0xFFFFFFFFu, s, o);
    float l = m + logf(s);

    out[(size_t)v * OUT_DIM + lane] = v0 - l;
    if (has1) out[(size_t)v * OUT_DIM + c1] = v1 - l;
}

// ---------------- launch ----------------
extern "C" void kernel_launch(void* const* d_in, const int* in_sizes, int n_in,
                              void* d_out, int out_size) {
    const float* x   = (const float*)d_in[0];
    const int*   src = (const int*)d_in[1];
    const int*   dst = (const int*)d_in[2];
    const float* Wl0 = (const float*)d_in[3];
    const float* bl0 = (const float*)d_in[4];
    const float* Wr0 = (const float*)d_in[5];
    const float* Wl1 = (const float*)d_in[6];
    const float* bl1 = (const float*)d_in[7];
    const float* Wr1 = (const float*)d_in[8];
    const float* Wl2 = (const float*)d_in[9];
    const float* bl2 = (const float*)d_in[10];
    const float* Wr2 = (const float*)d_in[11];
    float* out = (float*)d_out;

    void *pG, *pZ, *pA, *pB, *pCnt;
    cudaGetSymbolAddress(&pG, d_G);
    cudaGetSymbolAddress(&pZ, d_Z);
    cudaGetSymbolAddress(&pA, d_hA);
    cudaGetSymbolAddress(&pB, d_hB);
    cudaGetSymbolAddress(&pCnt, d_count);
    float* G  = (float*)pG;
    float* Z  = (float*)pZ;
    float* hA = (float*)pA;
    float* hB = (float*)pB;

    // CSR build
    cudaMemsetAsync(pCnt, 0, N_NODES * sizeof(int));
    count_kernel<<<(N_EDGES + 255) / 256, 256>>>(dst);
    scan_kernel<<<1, 1024>>>();
    scatter_kernel<<<(N_EDGES + 255) / 256, 256>>>(src, dst);

    const int gemm_grid = (N_NODES + 127) / 128;
    const int aggw_grid = (N_NODES * 32 + 255) / 256;

    // Layer 0
    gemm_n128<<<gemm_grid, 256>>>(x, Wl0, nullptr, G, N_NODES);
    gemm_n128<<<gemm_grid, 256>>>(x, Wr0, bl0,     Z, N_NODES);
    agg128_warp<<<aggw_grid, 256>>>(G, Z, hA, 1);

    // Layer 1
    gemm_n128<<<gemm_grid, 256>>>(hA, Wl1, nullptr, G, N_NODES);
    gemm_n128<<<gemm_grid, 256>>>(hA, Wr1, bl1,     Z, N_NODES);
    agg128_warp<<<aggw_grid, 256>>>(G, Z, hB, 1);

    // Layer 2 (width 47) + log_softmax
    gemm_n47<<<gemm_grid, 256>>>(hB, Wl2, nullptr, G, N_NODES);
    gemm_n47<<<gemm_grid, 256>>>(hB, Wr2, bl2,     Z, N_NODES);
    agg_lsm47_warp<<<aggw_grid, 256>>>(G, Z, out);
}

// round 4
// speedup vs baseline: 1.8088x; 1.6931x over previous
#include <cuda_runtime.h>
#include <cuda_bf16.h>
#include <mma.h>
#include <math.h>
#include <stdint.h>

using namespace nvcuda;

#define N_NODES 100000
#define N_EDGES 1600000
#define NPAD    100096            // 782 * 128
#define DIM 128
#define OUT_DIM 47
#define SMA 136                   // smem leading dim (bf16 elems): rows 272B apart

// ---------------- scratch ----------------
__device__ float d_G[(size_t)NPAD * DIM];
__device__ float d_Z[(size_t)NPAD * DIM];
__device__ __nv_bfloat16 d_Ah[(size_t)NPAD * DIM];
__device__ __nv_bfloat16 d_Al[(size_t)NPAD * DIM];
__device__ __nv_bfloat16 d_Bh[5 * 128 * 128];   // weight tiles [n][k]: Wl0,Wr0,Wl1,Wr1,(Wl2|Wr2)
__device__ __nv_bfloat16 d_Bl[5 * 128 * 128];
__device__ float d_invd[N_NODES];
__device__ int   d_count[N_NODES];
__device__ int   d_off[N_NODES + 1];
__device__ int   d_cursor[N_NODES];
__device__ int   d_esrc[N_EDGES];

// ---------------- CSR build ----------------
__global__ void count_kernel(const int* __restrict__ dst) {
    int e = blockIdx.x * blockDim.x + threadIdx.x;
    if (e < N_EDGES) atomicAdd(&d_count[dst[e]], 1);
}

__global__ void scan_kernel() {
    __shared__ int ssum[1024];
    const int t = threadIdx.x;
    const int CH = (N_NODES + 1023) / 1024;
    int lo = t * CH;
    int hi = lo + CH; if (hi > N_NODES) hi = N_NODES;
    if (lo > N_NODES) lo = N_NODES;
    int s = 0;
    for (int i = lo; i < hi; i++) s += d_count[i];
    ssum[t] = s;
    __syncthreads();
    for (int o = 1; o < 1024; o <<= 1) {
        int v = (t >= o) ? ssum[t - o] : 0;
        __syncthreads();
        ssum[t] += v;
        __syncthreads();
    }
    int run = (t > 0) ? ssum[t - 1] : 0;
    for (int i = lo; i < hi; i++) {
        int ci = d_count[i];
        d_off[i] = run;
        d_cursor[i] = run;
        d_invd[i] = (ci > 0) ? (1.0f / (float)ci) : 0.0f;
        run += ci;
    }
    if (t == 1023) d_off[N_NODES] = ssum[1023];
}

__global__ void scatter_kernel(const int* __restrict__ src, const int* __restrict__ dst) {
    int e = blockIdx.x * blockDim.x + threadIdx.x;
    if (e < N_EDGES) {
        int d = dst[e];
        int p = atomicAdd(&d_cursor[d], 1);
        d_esrc[p] = src[e];
    }
}

// ---------------- conversions (fp32 -> bf16 hi/lo) ----------------
__device__ __forceinline__ void split_bf16(float v, __nv_bfloat16& h, __nv_bfloat16& l) {
    h = __float2bfloat16_rn(v);
    l = __float2bfloat16_rn(v - __bfloat162float(h));
}

__global__ void xconv_kernel(const float* __restrict__ x,
                             __nv_bfloat16* __restrict__ oh, __nv_bfloat16* __restrict__ ol) {
    size_t i = (size_t)blockIdx.x * blockDim.x + threadIdx.x;
    if (i < (size_t)N_NODES * DIM) {
        __nv_bfloat16 h, l;
        split_bf16(x[i], h, l);
        oh[i] = h; ol[i] = l;
    }
}

// W[128 x nout] (row k, col n) -> tile[(row_off+n)][k] bf16 hi/lo, zero-pad n >= nout
__global__ void wconv_kernel(const float* __restrict__ W, int nout, int rows, int row_off,
                             __nv_bfloat16* __restrict__ bh, __nv_bfloat16* __restrict__ bl) {
    int i = blockIdx.x * blockDim.x + threadIdx.x;
    if (i >= rows * 128) return;
    int n = i >> 7, k = i & 127;
    float v = (n < nout) ? W[(size_t)k * nout + n] : 0.0f;
    __nv_bfloat16 h, l;
    split_bf16(v, h, l);
    bh[(size_t)(row_off + n) * 128 + k] = h;
    bl[(size_t)(row_off + n) * 128 + k] = l;
}

// ---------------- WMMA GEMM (bf16x3 compensated) ----------------
// C_p[M x 128] = A[M x 128] @ B_p^T, B_p stored [n][k].
// smem: Ah, Al, then per phase (Bh, Bl), all [128][SMA] bf16.
#define TILE_ELT (128 * SMA)                  // 17408 elems = 34816 B
#define GEMM_SMEM_MAX ((2 + 4) * TILE_ELT * 2)  // 208896 B (nphase = 2)

__global__ __launch_bounds__(256)
void gemm_wmma(const __nv_bfloat16* __restrict__ Ah, const __nv_bfloat16* __restrict__ Al,
               const __nv_bfloat16* __restrict__ Bh, const __nv_bfloat16* __restrict__ Bl,
               int nphase, float* __restrict__ C0, float* __restrict__ C1, int M) {
    extern __shared__ __nv_bfloat16 sm[];
    __nv_bfloat16* sAh = sm;
    __nv_bfloat16* sAl = sm + TILE_ELT;
    const int tid = threadIdx.x;
    const int m0 = blockIdx.x * 128;

    // A hi/lo tiles (guarded, zero-pad rows >= M)
#pragma unroll
    for (int i = 0; i < 8; i++) {
        int u = i * 256 + tid;                 // 0..2047 uint4 units
        int row = u >> 4, c8 = (u & 15) * 8;
        uint4 vh = make_uint4(0u, 0u, 0u, 0u), vl = vh;
        if (m0 + row < M) {
            vh = *(const uint4*)(Ah + (size_t)(m0 + row) * 128 + c8);
            vl = *(const uint4*)(Al + (size_t)(m0 + row) * 128 + c8);
        }
        *(uint4*)(sAh + row * SMA + c8) = vh;
        *(uint4*)(sAl + row * SMA + c8) = vl;
    }
    // B tiles (weights fully padded in global, no guard)
    for (int p = 0; p < nphase; p++) {
        __nv_bfloat16* dh = sm + (2 + 2 * p) * TILE_ELT;
        __nv_bfloat16* dl = dh + TILE_ELT;
        const __nv_bfloat16* gh = Bh + (size_t)p * 16384;
        const __nv_bfloat16* gl = Bl + (size_t)p * 16384;
#pragma unroll
        for (int i = 0; i < 8; i++) {
            int u = i * 256 + tid;
            int row = u >> 4, c8 = (u & 15) * 8;
            *(uint4*)(dh + row * SMA + c8) = *(const uint4*)(gh + row * 128 + c8);
            *(uint4*)(dl + row * SMA + c8) = *(const uint4*)(gl + row * 128 + c8);
        }
    }
    __syncthreads();

    const int wid = tid >> 5;
    const int wm = (wid & 3) * 32;     // 4 warps along m
    const int wn = (wid >> 2) * 64;    // 2 warps along n

    for (int p = 0; p < nphase; p++) {
        float* C = p ? C1 : C0;
        const __nv_bfloat16* sBh = sm + (2 + 2 * p) * TILE_ELT;
        const __nv_bfloat16* sBl = sBh + TILE_ELT;

        wmma::fragment<wmma::accumulator, 16, 16, 16, float> acc[2][4];
#pragma unroll
        for (int i = 0; i < 2; i++)
#pragma unroll
            for (int j = 0; j < 4; j++) wmma::fill_fragment(acc[i][j], 0.0f);

#pragma unroll
        for (int ks = 0; ks < 8; ks++) {
            wmma::fragment<wmma::matrix_a, 16, 16, 16, __nv_bfloat16, wmma::row_major> fah[2], fal[2];
            wmma::fragment<wmma::matrix_b, 16, 16, 16, __nv_bfloat16, wmma::col_major> fbh[4], fbl[4];
#pragma unroll
            for (int i = 0; i < 2; i++) {
                wmma::load_matrix_sync(fah[i], sAh + (wm + i * 16) * SMA + ks * 16, SMA);
                wmma::load_matrix_sync(fal[i], sAl + (wm + i * 16) * SMA + ks * 16, SMA);
            }
#pragma unroll
            for (int j = 0; j < 4; j++) {
                wmma::load_matrix_sync(fbh[j], sBh + (wn + j * 16) * SMA + ks * 16, SMA);
                wmma::load_matrix_sync(fbl[j], sBl + (wn + j * 16) * SMA + ks * 16, SMA);
            }
#pragma unroll
            for (int i = 0; i < 2; i++)
#pragma unroll
                for (int j = 0; j < 4; j++) {
                    wmma::mma_sync(acc[i][j], fah[i], fbh[j], acc[i][j]);
                    wmma::mma_sync(acc[i][j], fal[i], fbh[j], acc[i][j]);
                    wmma::mma_sync(acc[i][j], fah[i], fbl[j], acc[i][j]);
                }
        }
#pragma unroll
        for (int i = 0; i < 2; i++)
#pragma unroll
            for (int j = 0; j < 4; j++)
                wmma::store_matrix_sync(C + (size_t)(m0 + wm + i * 16) * 128 + wn + j * 16,
                                        acc[i][j], 128, wmma::mem_row_major);
    }
}

// ---------------- aggregation, warp per node; adds bias; emits bf16 hi/lo ----------
__global__ void agg128_warp(const float* __restrict__ G, const float* __restrict__ Z,
                            const float* __restrict__ bias,
                            __nv_bfloat16* __restrict__ oh, __nv_bfloat16* __restrict__ ol) {
    int w = (blockIdx.x * blockDim.x + threadIdx.x) >> 5;
    int lane = threadIdx.x & 31;
    if (w >= N_NODES) return;
    const int e0 = d_off[w], e1 = d_off[w + 1];
    const float4* Gv = (const float4*)G;
    float4 a0 = make_float4(0.f, 0.f, 0.f, 0.f);
    float4 a1 = make_float4(0.f, 0.f, 0.f, 0.f);
    int i = e0;
    for (; i + 2 <= e1; i += 2) {
        int s0 = d_esrc[i], s1 = d_esrc[i + 1];
        float4 r0 = __ldg(&Gv[(size_t)s0 * 32 + lane]);
        float4 r1 = __ldg(&Gv[(size_t)s1 * 32 + lane]);
        a0.x += r0.x; a0.y += r0.y; a0.z += r0.z; a0.w += r0.w;
        a1.x += r1.x; a1.y += r1.y; a1.z += r1.z; a1.w += r1.w;
    }
    if (i < e1) {
        float4 r0 = __ldg(&Gv[(size_t)d_esrc[i] * 32 + lane]);
        a0.x += r0.x; a0.y += r0.y; a0.z += r0.z; a0.w += r0.w;
    }
    float inv = d_invd[w];
    float4 z = __ldg(&((const float4*)Z)[(size_t)w * 32 + lane]);
    float4 b = __ldg(&((const float4*)bias)[lane]);
    float o[4];
    o[0] = fmaxf(z.x + b.x + inv * (a0.x + a1.x), 0.f);
    o[1] = fmaxf(z.y + b.y + inv * (a0.y + a1.y), 0.f);
    o[2] = fmaxf(z.z + b.z + inv * (a0.z + a1.z), 0.f);
    o[3] = fmaxf(z.w + b.w + inv * (a0.w + a1.w), 0.f);

    __nv_bfloat16 hb[4], lb[4];
#pragma unroll
    for (int j = 0; j < 4; j++) split_bf16(o[j], hb[j], lb[j]);
    *(uint2*)&oh[(size_t)w * 128 + lane * 4] = *(uint2*)hb;
    *(uint2*)&ol[(size_t)w * 128 + lane * 4] = *(uint2*)lb;
}

// ---------------- layer-2 agg + log_softmax, warp per node ----------------
// GZ row layout: cols [0,47) = G (gathered over neighbors), cols [64,111) = Z (self)
__global__ void agg_lsm47_warp(const float* __restrict__ GZ, const float* __restrict__ bias,
                               float* __restrict__ out) {
    int v = (blockIdx.x * blockDim.x + threadIdx.x) >> 5;
    int lane = threadIdx.x & 31;
    if (v >= N_NODES) return;
    const int e0 = d_off[v], e1 = d_off[v + 1];
    const int c1 = 32 + lane;
    const bool has1 = c1 < OUT_DIM;

    float a0 = 0.f, a1 = 0.f, b0 = 0.f, b1 = 0.f;
    int i = e0;
    for (; i + 2 <= e1; i += 2) {
        const float* g = GZ + (size_t)d_esrc[i] * 128;
        const float* h = GZ + (size_t)d_esrc[i + 1] * 128;
        a0 += __ldg(&g[lane]);
        b0 += __ldg(&h[lane]);
        if (has1) {
            a1 += __ldg(&g[c1]);
            b1 += __ldg(&h[c1]);
        }
    }
    if (i < e1) {
        const float* g = GZ + (size_t)d_esrc[i] * 128;
        a0 += __ldg(&g[lane]);
        if (has1) a1 += __ldg(&g[c1]);
    }
    a0 += b0; a1 += b1;

    float inv = d_invd[v];
    const float* z = GZ + (size_t)v * 128 + 64;
    float v0 = z[lane] + bias[lane] + inv * a0;
    float v1 = has1 ? (z[c1] + bias[c1] + inv * a1) : -INFINITY;

    float m = fmaxf(v0, v1);
#pragma unroll
    for (int o = 16; o > 0; o >>= 1) m = fmaxf(m, __shfl_xor_sync(0xFFFFFFFFu, m, o));
    float s = expf(v0 - m) + (has1 ? expf(v1 - m) : 0.f);
#pragma unroll
    for (int o = 16; o > 0; o >>= 1) s += __shfl_xor_sync(0xFFFFFFFFu, s, o);
    float l = m + logf(s);

    out[(size_t)v * OUT_DIM + lane] = v0 - l;
    if (has1) out[(size_t)v * OUT_DIM + c1] = v1 - l;
}

// ---------------- launch ----------------
extern "C" void kernel_launch(void* const* d_in, const int* in_sizes, int n_in,
                              void* d_out, int out_size) {
    const float* x   = (const float*)d_in[0];
    const int*   src = (const int*)d_in[1];
    const int*   dst = (const int*)d_in[2];
    const float* Wl0 = (const float*)d_in[3];
    const float* bl0 = (const float*)d_in[4];
    const float* Wr0 = (const float*)d_in[5];
    const float* Wl1 = (const float*)d_in[6];
    const float* bl1 = (const float*)d_in[7];
    const float* Wr1 = (const float*)d_in[8];
    const float* Wl2 = (const float*)d_in[9];
    const float* bl2 = (const float*)d_in[10];
    const float* Wr2 = (const float*)d_in[11];
    float* out = (float*)d_out;

    void *pG, *pZ, *pAh, *pAl, *pBh, *pBl, *pCnt;
    cudaGetSymbolAddress(&pG, d_G);
    cudaGetSymbolAddress(&pZ, d_Z);
    cudaGetSymbolAddress(&pAh, d_Ah);
    cudaGetSymbolAddress(&pAl, d_Al);
    cudaGetSymbolAddress(&pBh, d_Bh);
    cudaGetSymbolAddress(&pBl, d_Bl);
    cudaGetSymbolAddress(&pCnt, d_count);
    float* G = (float*)pG;
    float* Z = (float*)pZ;
    __nv_bfloat16* Ah = (__nv_bfloat16*)pAh;
    __nv_bfloat16* Al = (__nv_bfloat16*)pAl;
    __nv_bfloat16* Bh = (__nv_bfloat16*)pBh;
    __nv_bfloat16* Bl = (__nv_bfloat16*)pBl;

    cudaFuncSetAttribute(gemm_wmma, cudaFuncAttributeMaxDynamicSharedMemorySize,
                         GEMM_SMEM_MAX);

    // CSR build
    cudaMemsetAsync(pCnt, 0, N_NODES * sizeof(int));
    count_kernel<<<(N_EDGES + 255) / 256, 256>>>(dst);
    scan_kernel<<<1, 1024>>>();
    scatter_kernel<<<(N_EDGES + 255) / 256, 256>>>(src, dst);

    // weight tiles: 0:Wl0 1:Wr0 2:Wl1 3:Wr1 4:(Wl2 rows 0-63 | Wr2 rows 64-127)
    wconv_kernel<<<64, 256>>>(Wl0, DIM, 128, 0, Bh + 0 * 16384, Bl + 0 * 16384);
    wconv_kernel<<<64, 256>>>(Wr0, DIM, 128, 0, Bh + 1 * 16384, Bl + 1 * 16384);
    wconv_kernel<<<64, 256>>>(Wl1, DIM, 128, 0, Bh + 2 * 16384, Bl + 2 * 16384);
    wconv_kernel<<<64, 256>>>(Wr1, DIM, 128, 0, Bh + 3 * 16384, Bl + 3 * 16384);
    wconv_kernel<<<32, 256>>>(Wl2, OUT_DIM, 64, 0,  Bh + 4 * 16384, Bl + 4 * 16384);
    wconv_kernel<<<32, 256>>>(Wr2, OUT_DIM, 64, 64, Bh + 4 * 16384, Bl + 4 * 16384);
    xconv_kernel<<<(N_NODES * DIM + 255) / 256, 256>>>(x, Ah, Al);

    const int gemm_grid = NPAD / 128;   // 782
    const int aggw_grid = (N_NODES * 32 + 255) / 256;
    const size_t smem2 = (size_t)(2 + 4) * TILE_ELT * 2;
    const size_t smem1 = (size_t)(2 + 2) * TILE_ELT * 2;

    // Layer 0: phase0 -> G (x@Wl0), phase1 -> Z (x@Wr0)
    gemm_wmma<<<gemm_grid, 256, smem2>>>(Ah, Al, Bh, Bl, 2, G, Z, N_NODES);
    agg128_warp<<<aggw_grid, 256>>>(G, Z, bl0, Ah, Al);

    // Layer 1
    gemm_wmma<<<gemm_grid, 256, smem2>>>(Ah, Al, Bh + 2 * 16384, Bl + 2 * 16384, 2, G, Z, N_NODES);
    agg128_warp<<<aggw_grid, 256>>>(G, Z, bl1, Ah, Al);

    // Layer 2: single phase, cols [0,64)=h@Wl2, [64,128)=h@Wr2, into G
    gemm_wmma<<<gemm_grid, 256, smem1>>>(Ah, Al, Bh + 4 * 16384, Bl + 4 * 16384, 1, G, nullptr, N_NODES);
    agg_lsm47_warp<<<aggw_grid, 256>>>(G, bl2, out);
}

// round 5
// speedup vs baseline: 1.8728x; 1.0354x over previous
#include <cuda_runtime.h>
#include <cuda_bf16.h>
#include <cuda_fp16.h>
#include <mma.h>
#include <math.h>
#include <stdint.h>

using namespace nvcuda;

#define N_NODES 100000
#define N_EDGES 1600000
#define NPAD    100096            // 782 * 128
#define DIM 128
#define OUT_DIM 47
#define SMA 136                   // smem leading dim (bf16 elems)
#define STG 132                   // fp32 staging leading dim

// ---------------- scratch ----------------
__device__ __half d_Gh[(size_t)NPAD * DIM];     // gather matrix (fp16)
__device__ float d_Z[(size_t)NPAD * DIM];       // self term (fp32)
__device__ __nv_bfloat16 d_Ah[(size_t)NPAD * DIM];
__device__ __nv_bfloat16 d_Al[(size_t)NPAD * DIM];
__device__ __nv_bfloat16 d_Bh[5 * 128 * 128];
__device__ __nv_bfloat16 d_Bl[5 * 128 * 128];
__device__ float d_invd[N_NODES];
__device__ int   d_count[N_NODES];
__device__ int   d_off[N_NODES + 1];
__device__ int   d_cursor[N_NODES];
__device__ int   d_esrc[N_EDGES];

// ---------------- CSR build ----------------
__global__ void count_kernel(const int* __restrict__ dst) {
    int e = blockIdx.x * blockDim.x + threadIdx.x;
    if (e < N_EDGES) atomicAdd(&d_count[dst[e]], 1);
}

__global__ void scan_kernel() {
    __shared__ int ssum[1024];
    const int t = threadIdx.x;
    const int CH = (N_NODES + 1023) / 1024;
    int lo = t * CH;
    int hi = lo + CH; if (hi > N_NODES) hi = N_NODES;
    if (lo > N_NODES) lo = N_NODES;
    int s = 0;
    for (int i = lo; i < hi; i++) s += d_count[i];
    ssum[t] = s;
    __syncthreads();
    for (int o = 1; o < 1024; o <<= 1) {
        int v = (t >= o) ? ssum[t - o] : 0;
        __syncthreads();
        ssum[t] += v;
        __syncthreads();
    }
    int run = (t > 0) ? ssum[t - 1] : 0;
    for (int i = lo; i < hi; i++) {
        int ci = d_count[i];
        d_off[i] = run;
        d_cursor[i] = run;
        d_invd[i] = (ci > 0) ? (1.0f / (float)ci) : 0.0f;
        run += ci;
    }
    if (t == 1023) d_off[N_NODES] = ssum[1023];
}

__global__ void scatter_kernel(const int* __restrict__ src, const int* __restrict__ dst) {
    int e = blockIdx.x * blockDim.x + threadIdx.x;
    if (e < N_EDGES) {
        int d = dst[e];
        int p = atomicAdd(&d_cursor[d], 1);
        d_esrc[p] = src[e];
    }
}

// ---------------- conversions ----------------
__device__ __forceinline__ void split_bf16(float v, __nv_bfloat16& h, __nv_bfloat16& l) {
    h = __float2bfloat16_rn(v);
    l = __float2bfloat16_rn(v - __bfloat162float(h));
}

__global__ void xconv_kernel(const float* __restrict__ x,
                             __nv_bfloat16* __restrict__ oh, __nv_bfloat16* __restrict__ ol) {
    size_t i = (size_t)blockIdx.x * blockDim.x + threadIdx.x;
    if (i < (size_t)N_NODES * DIM) {
        __nv_bfloat16 h, l;
        split_bf16(x[i], h, l);
        oh[i] = h; ol[i] = l;
    }
}

// all 5 weight tiles in one launch; tile layout [n][k] bf16 hi/lo
__global__ void wconv_all(const float* __restrict__ Wl0, const float* __restrict__ Wr0,
                          const float* __restrict__ Wl1, const float* __restrict__ Wr1,
                          const float* __restrict__ Wl2, const float* __restrict__ Wr2,
                          __nv_bfloat16* __restrict__ bh, __nv_bfloat16* __restrict__ bl) {
    int i = blockIdx.x * blockDim.x + threadIdx.x;
    if (i >= 5 * 16384) return;
    int t = i >> 14, r = (i >> 7) & 127, k = i & 127;
    float v = 0.0f;
    if (t == 0) v = Wl0[(size_t)k * 128 + r];
    else if (t == 1) v = Wr0[(size_t)k * 128 + r];
    else if (t == 2) v = Wl1[(size_t)k * 128 + r];
    else if (t == 3) v = Wr1[(size_t)k * 128 + r];
    else {
        if (r < 64) { if (r < OUT_DIM) v = Wl2[(size_t)k * OUT_DIM + r]; }
        else        { if (r - 64 < OUT_DIM) v = Wr2[(size_t)k * OUT_DIM + (r - 64)]; }
    }
    __nv_bfloat16 h, l;
    split_bf16(v, h, l);
    bh[i] = h; bl[i] = l;
}

// ---------------- WMMA GEMM (bf16x3 compensated) ----------------
// nphase==2: phase0 -> Gh fp16 (stride 128), phase1 -> Z fp32 (stride 128, direct)
// nphase==1: cols 0-63 -> Gh fp16 (stride 64), cols 64-127 -> Z fp32 (stride 64)
#define TILE_ELT (128 * SMA)
#define GEMM_SMEM_MAX ((2 + 4) * TILE_ELT * 2)

__global__ __launch_bounds__(256)
void gemm_wmma(const __nv_bfloat16* __restrict__ Ah, const __nv_bfloat16* __restrict__ Al,
               const __nv_bfloat16* __restrict__ Bh, const __nv_bfloat16* __restrict__ Bl,
               int nphase, __half* __restrict__ Gh, float* __restrict__ Z, int M) {
    extern __shared__ __nv_bfloat16 sm[];
    __nv_bfloat16* sAh = sm;
    __nv_bfloat16* sAl = sm + TILE_ELT;
    const int tid = threadIdx.x;
    const int m0 = blockIdx.x * 128;

#pragma unroll
    for (int i = 0; i < 8; i++) {
        int u = i * 256 + tid;
        int row = u >> 4, c8 = (u & 15) * 8;
        uint4 vh = make_uint4(0u, 0u, 0u, 0u), vl = vh;
        if (m0 + row < M) {
            vh = *(const uint4*)(Ah + (size_t)(m0 + row) * 128 + c8);
            vl = *(const uint4*)(Al + (size_t)(m0 + row) * 128 + c8);
        }
        *(uint4*)(sAh + row * SMA + c8) = vh;
        *(uint4*)(sAl + row * SMA + c8) = vl;
    }
    for (int p = 0; p < nphase; p++) {
        __nv_bfloat16* dh = sm + (2 + 2 * p) * TILE_ELT;
        __nv_bfloat16* dl = dh + TILE_ELT;
        const __nv_bfloat16* gh = Bh + (size_t)p * 16384;
        const __nv_bfloat16* gl = Bl + (size_t)p * 16384;
#pragma unroll
        for (int i = 0; i < 8; i++) {
            int u = i * 256 + tid;
            int row = u >> 4, c8 = (u & 15) * 8;
            *(uint4*)(dh + row * SMA + c8) = *(const uint4*)(gh + row * 128 + c8);
            *(uint4*)(dl + row * SMA + c8) = *(const uint4*)(gl + row * 128 + c8);
        }
    }
    __syncthreads();

    const int wid = tid >> 5;
    const int wm = (wid & 3) * 32;
    const int wn = (wid >> 2) * 64;

    for (int p = 0; p < nphase; p++) {
        const __nv_bfloat16* sBh = sm + (2 + 2 * p) * TILE_ELT;
        const __nv_bfloat16* sBl = sBh + TILE_ELT;

        wmma::fragment<wmma::accumulator, 16, 16, 16, float> acc[2][4];
#pragma unroll
        for (int i = 0; i < 2; i++)
#pragma unroll
            for (int j = 0; j < 4; j++) wmma::fill_fragment(acc[i][j], 0.0f);

#pragma unroll
        for (int ks = 0; ks < 8; ks++) {
            wmma::fragment<wmma::matrix_a, 16, 16, 16, __nv_bfloat16, wmma::row_major> fah[2], fal[2];
            wmma::fragment<wmma::matrix_b, 16, 16, 16, __nv_bfloat16, wmma::col_major> fbh[4], fbl[4];
#pragma unroll
            for (int i = 0; i < 2; i++) {
                wmma::load_matrix_sync(fah[i], sAh + (wm + i * 16) * SMA + ks * 16, SMA);
                wmma::load_matrix_sync(fal[i], sAl + (wm + i * 16) * SMA + ks * 16, SMA);
            }
#pragma unroll
            for (int j = 0; j < 4; j++) {
                wmma::load_matrix_sync(fbh[j], sBh + (wn + j * 16) * SMA + ks * 16, SMA);
                wmma::load_matrix_sync(fbl[j], sBl + (wn + j * 16) * SMA + ks * 16, SMA);
            }
#pragma unroll
            for (int i = 0; i < 2; i++)
#pragma unroll
                for (int j = 0; j < 4; j++) {
                    wmma::mma_sync(acc[i][j], fah[i], fbh[j], acc[i][j]);
                    wmma::mma_sync(acc[i][j], fal[i], fbh[j], acc[i][j]);
                    wmma::mma_sync(acc[i][j], fah[i], fbl[j], acc[i][j]);
                }
        }

        const bool g_phase = (p == 0);   // phase0 always produces the gather matrix
        if (g_phase) {
            // stage fp32 in this phase's B area (done with its MMA reads after sync)
            float* stage = (float*)(sm + (2 + 2 * p) * TILE_ELT);
            __syncthreads();
#pragma unroll
            for (int i = 0; i < 2; i++)
#pragma unroll
                for (int j = 0; j < 4; j++)
                    wmma::store_matrix_sync(stage + (wm + i * 16) * STG + wn + j * 16,
                                            acc[i][j], STG, wmma::mem_row_major);
            __syncthreads();

            if (nphase == 2) {
                // full 128 cols -> fp16, stride 128
                for (int i = tid; i < 128 * 16; i += 256) {
                    int r = i >> 4, c8 = (i & 15) * 8;
                    if (m0 + r < M) {
                        __half h8[8];
#pragma unroll
                        for (int j = 0; j < 8; j++)
                            h8[j] = __float2half_rn(stage[r * STG + c8 + j]);
                        *(uint4*)(Gh + (size_t)(m0 + r) * 128 + c8) = *(uint4*)h8;
                    }
                }
            } else {
                // cols 0-63 -> fp16 stride 64; cols 64-127 -> fp32 Z stride 64
                for (int i = tid; i < 128 * 8; i += 256) {
                    int r = i >> 3, c8 = (i & 7) * 8;
                    if (m0 + r < M) {
                        __half h8[8];
#pragma unroll
                        for (int j = 0; j < 8; j++)
                            h8[j] = __float2half_rn(stage[r * STG + c8 + j]);
                        *(uint4*)(Gh + (size_t)(m0 + r) * 64 + c8) = *(uint4*)h8;
                    }
                }
                for (int i = tid; i < 128 * 16; i += 256) {
                    int r = i >> 4, c4 = (i & 15) * 4;
                    if (m0 + r < M)
                        *(float4*)(Z + (size_t)(m0 + r) * 64 + c4) =
                            *(float4*)(stage + r * STG + 64 + c4);
                }
            }
        } else {
            // phase1: Z fp32 direct
#pragma unroll
            for (int i = 0; i < 2; i++)
#pragma unroll
                for (int j = 0; j < 4; j++)
                    wmma::store_matrix_sync(Z + (size_t)(m0 + wm + i * 16) * 128 + wn + j * 16,
                                            acc[i][j], 128, wmma::mem_row_major);
        }
    }
}

// ---------------- aggregation, warp per node (fp16 gather); emits bf16 hi/lo ----------
__global__ void agg128_warp(const __half* __restrict__ G, const float* __restrict__ Z,
                            const float* __restrict__ bias,
                            __nv_bfloat16* __restrict__ oh, __nv_bfloat16* __restrict__ ol) {
    int w = (blockIdx.x * blockDim.x + threadIdx.x) >> 5;
    int lane = threadIdx.x & 31;
    if (w >= N_NODES) return;
    const int e0 = d_off[w], e1 = d_off[w + 1];
    const uint2* Gv = (const uint2*)G;   // 4 halves per lane
    float a0[4] = {0.f, 0.f, 0.f, 0.f};
    float a1[4] = {0.f, 0.f, 0.f, 0.f};
    int i = e0;
    for (; i + 2 <= e1; i += 2) {
        uint2 u0 = __ldg(&Gv[(size_t)d_esrc[i] * 32 + lane]);
        uint2 u1 = __ldg(&Gv[(size_t)d_esrc[i + 1] * 32 + lane]);
        float2 p0 = __half22float2(*(const __half2*)&u0.x);
        float2 p1 = __half22float2(*(const __half2*)&u0.y);
        float2 q0 = __half22float2(*(const __half2*)&u1.x);
        float2 q1 = __half22float2(*(const __half2*)&u1.y);
        a0[0] += p0.x; a0[1] += p0.y; a0[2] += p1.x; a0[3] += p1.y;
        a1[0] += q0.x; a1[1] += q0.y; a1[2] += q1.x; a1[3] += q1.y;
    }
    if (i < e1) {
        uint2 u0 = __ldg(&Gv[(size_t)d_esrc[i] * 32 + lane]);
        float2 p0 = __half22float2(*(const __half2*)&u0.x);
        float2 p1 = __half22float2(*(const __half2*)&u0.y);
        a0[0] += p0.x; a0[1] += p0.y; a0[2] += p1.x; a0[3] += p1.y;
    }
    float inv = d_invd[w];
    float4 z = __ldg(&((const float4*)Z)[(size_t)w * 32 + lane]);
    float4 b = __ldg(&((const float4*)bias)[lane]);
    float o[4];
    o[0] = fmaxf(z.x + b.x + inv * (a0[0] + a1[0]), 0.f);
    o[1] = fmaxf(z.y + b.y + inv * (a0[1] + a1[1]), 0.f);
    o[2] = fmaxf(z.z + b.z + inv * (a0[2] + a1[2]), 0.f);
    o[3] = fmaxf(z.w + b.w + inv * (a0[3] + a1[3]), 0.f);

    __nv_bfloat16 hb[4], lb[4];
#pragma unroll
    for (int j = 0; j < 4; j++) split_bf16(o[j], hb[j], lb[j]);
    *(uint2*)&oh[(size_t)w * 128 + lane * 4] = *(uint2*)hb;
    *(uint2*)&ol[(size_t)w * 128 + lane * 4] = *(uint2*)lb;
}

// ---------------- layer-2 agg + log_softmax (fp16 gather stride 64, fp32 Z stride 64) --
__global__ void agg_lsm47_warp(const __half* __restrict__ G, const float* __restrict__ Z,
                               const float* __restrict__ bias, float* __restrict__ out) {
    int v = (blockIdx.x * blockDim.x + threadIdx.x) >> 5;
    int lane = threadIdx.x & 31;
    if (v >= N_NODES) return;
    const int e0 = d_off[v], e1 = d_off[v + 1];
    const int c1 = 32 + lane;
    const bool has1 = c1 < OUT_DIM;

    float a0 = 0.f, a1 = 0.f, b0 = 0.f, b1 = 0.f;
    int i = e0;
    for (; i + 2 <= e1; i += 2) {
        const __half* g = G + (size_t)d_esrc[i] * 64;
        const __half* h = G + (size_t)d_esrc[i + 1] * 64;
        a0 += __half2float(__ldg(&g[lane]));
        b0 += __half2float(__ldg(&h[lane]));
        if (has1) {
            a1 += __half2float(__ldg(&g[c1]));
            b1 += __half2float(__ldg(&h[c1]));
        }
    }
    if (i < e1) {
        const __half* g = G + (size_t)d_esrc[i] * 64;
        a0 += __half2float(__ldg(&g[lane]));
        if (has1) a1 += __half2float(__ldg(&g[c1]));
    }
    a0 += b0; a1 += b1;

    float inv = d_invd[v];
    const float* z = Z + (size_t)v * 64;
    float v0 = z[lane] + bias[lane] + inv * a0;
    float v1 = has1 ? (z[c1] + bias[c1] + inv * a1) : -INFINITY;

    float m = fmaxf(v0, v1);
#pragma unroll
    for (int o = 16; o > 0; o >>= 1) m = fmaxf(m, __shfl_xor_sync(0xFFFFFFFFu, m, o));
    float s = expf(v0 - m) + (has1 ? expf(v1 - m) : 0.f);
#pragma unroll
    for (int o = 16; o > 0; o >>= 1) s += __shfl_xor_sync(0xFFFFFFFFu, s, o);
    float l = m + logf(s);

    out[(size_t)v * OUT_DIM + lane] = v0 - l;
    if (has1) out[(size_t)v * OUT_DIM + c1] = v1 - l;
}

// ---------------- launch ----------------
extern "C" void kernel_launch(void* const* d_in, const int* in_sizes, int n_in,
                              void* d_out, int out_size) {
    const float* x   = (const float*)d_in[0];
    const int*   src = (const int*)d_in[1];
    const int*   dst = (const int*)d_in[2];
    const float* Wl0 = (const float*)d_in[3];
    const float* bl0 = (const float*)d_in[4];
    const float* Wr0 = (const float*)d_in[5];
    const float* Wl1 = (const float*)d_in[6];
    const float* bl1 = (const float*)d_in[7];
    const float* Wr1 = (const float*)d_in[8];
    const float* Wl2 = (const float*)d_in[9];
    const float* bl2 = (const float*)d_in[10];
    const float* Wr2 = (const float*)d_in[11];
    float* out = (float*)d_out;

    void *pGh, *pZ, *pAh, *pAl, *pBh, *pBl, *pCnt;
    cudaGetSymbolAddress(&pGh, d_Gh);
    cudaGetSymbolAddress(&pZ, d_Z);
    cudaGetSymbolAddress(&pAh, d_Ah);
    cudaGetSymbolAddress(&pAl, d_Al);
    cudaGetSymbolAddress(&pBh, d_Bh);
    cudaGetSymbolAddress(&pBl, d_Bl);
    cudaGetSymbolAddress(&pCnt, d_count);
    __half* Gh = (__half*)pGh;
    float* Z = (float*)pZ;
    __nv_bfloat16* Ah = (__nv_bfloat16*)pAh;
    __nv_bfloat16* Al = (__nv_bfloat16*)pAl;
    __nv_bfloat16* Bh = (__nv_bfloat16*)pBh;
    __nv_bfloat16* Bl = (__nv_bfloat16*)pBl;

    cudaFuncSetAttribute(gemm_wmma, cudaFuncAttributeMaxDynamicSharedMemorySize,
                         GEMM_SMEM_MAX);

    // CSR build
    cudaMemsetAsync(pCnt, 0, N_NODES * sizeof(int));
    count_kernel<<<(N_EDGES + 255) / 256, 256>>>(dst);
    scan_kernel<<<1, 1024>>>();
    scatter_kernel<<<(N_EDGES + 255) / 256, 256>>>(src, dst);

    wconv_all<<<(5 * 16384 + 255) / 256, 256>>>(Wl0, Wr0, Wl1, Wr1, Wl2, Wr2, Bh, Bl);
    xconv_kernel<<<(N_NODES * DIM + 255) / 256, 256>>>(x, Ah, Al);

    const int gemm_grid = NPAD / 128;
    const int aggw_grid = (N_NODES * 32 + 255) / 256;
    const size_t smem2 = (size_t)(2 + 4) * TILE_ELT * 2;
    const size_t smem1 = (size_t)(2 + 2) * TILE_ELT * 2;

    // Layer 0
    gemm_wmma<<<gemm_grid, 256, smem2>>>(Ah, Al, Bh, Bl, 2, Gh, Z, N_NODES);
    agg128_warp<<<aggw_grid, 256>>>(Gh, Z, bl0, Ah, Al);

    // Layer 1
    gemm_wmma<<<gemm_grid, 256, smem2>>>(Ah, Al, Bh + 2 * 16384, Bl + 2 * 16384, 2, Gh, Z, N_NODES);
    agg128_warp<<<aggw_grid, 256>>>(Gh, Z, bl1, Ah, Al);

    // Layer 2
    gemm_wmma<<<gemm_grid, 256, smem1>>>(Ah, Al, Bh + 4 * 16384, Bl + 4 * 16384, 1, Gh, Z, N_NODES);
    agg_lsm47_warp<<<aggw_grid, 256>>>(Gh, Z, bl2, out);
}

// round 6
// speedup vs baseline: 2.0013x; 1.0686x over previous
#include <cuda_runtime.h>
#include <cuda_bf16.h>
#include <cuda_fp16.h>
#include <mma.h>
#include <math.h>
#include <stdint.h>

using namespace nvcuda;

#define N_NODES 100000
#define N_EDGES 1600000
#define NPAD    100096            // 782 * 128
#define DIM 128
#define OUT_DIM 47
#define SMA 136                   // smem leading dim (bf16 elems)
#define STG 132                   // fp32 staging leading dim

// ---------------- scratch ----------------
__device__ __half d_Gh[(size_t)NPAD * DIM];     // gather matrix (fp16)
__device__ float d_Z[(size_t)NPAD * DIM];       // self term (fp32)
__device__ __nv_bfloat16 d_Ah[(size_t)NPAD * DIM];
__device__ __nv_bfloat16 d_Al[(size_t)NPAD * DIM];
__device__ __nv_bfloat16 d_Bh[5 * 128 * 128];
__device__ __nv_bfloat16 d_Bl[5 * 128 * 128];
__device__ float d_invd[N_NODES];
__device__ int   d_count[N_NODES];
__device__ int   d_off[N_NODES + 1];
__device__ int   d_cursor[N_NODES];
__device__ int   d_esrc[N_EDGES];

// ---------------- CSR build ----------------
__global__ void count_kernel(const int* __restrict__ dst) {
    int e = blockIdx.x * blockDim.x + threadIdx.x;
    if (e < N_EDGES) atomicAdd(&d_count[dst[e]], 1);
}

__global__ void scan_kernel() {
    __shared__ int ssum[1024];
    const int t = threadIdx.x;
    const int CH = (N_NODES + 1023) / 1024;
    int lo = t * CH;
    int hi = lo + CH; if (hi > N_NODES) hi = N_NODES;
    if (lo > N_NODES) lo = N_NODES;
    int s = 0;
    for (int i = lo; i < hi; i++) s += d_count[i];
    ssum[t] = s;
    __syncthreads();
    for (int o = 1; o < 1024; o <<= 1) {
        int v = (t >= o) ? ssum[t - o] : 0;
        __syncthreads();
        ssum[t] += v;
        __syncthreads();
    }
    int run = (t > 0) ? ssum[t - 1] : 0;
    for (int i = lo; i < hi; i++) {
        int ci = d_count[i];
        d_off[i] = run;
        d_cursor[i] = run;
        d_invd[i] = (ci > 0) ? (1.0f / (float)ci) : 0.0f;
        run += ci;
    }
    if (t == 1023) d_off[N_NODES] = ssum[1023];
}

__global__ void scatter_kernel(const int* __restrict__ src, const int* __restrict__ dst) {
    int e = blockIdx.x * blockDim.x + threadIdx.x;
    if (e < N_EDGES) {
        int d = dst[e];
        int p = atomicAdd(&d_cursor[d], 1);
        d_esrc[p] = src[e];
    }
}

// ---------------- conversions ----------------
__device__ __forceinline__ void split_bf16(float v, __nv_bfloat16& h, __nv_bfloat16& l) {
    h = __float2bfloat16_rn(v);
    l = __float2bfloat16_rn(v - __bfloat162float(h));
}

// all 5 weight tiles in one launch; tile layout [n][k] bf16 hi/lo
__global__ void wconv_all(const float* __restrict__ Wl0, const float* __restrict__ Wr0,
                          const float* __restrict__ Wl1, const float* __restrict__ Wr1,
                          const float* __restrict__ Wl2, const float* __restrict__ Wr2,
                          __nv_bfloat16* __restrict__ bh, __nv_bfloat16* __restrict__ bl) {
    int i = blockIdx.x * blockDim.x + threadIdx.x;
    if (i >= 5 * 16384) return;
    int t = i >> 14, r = (i >> 7) & 127, k = i & 127;
    float v = 0.0f;
    if (t == 0) v = Wl0[(size_t)k * 128 + r];
    else if (t == 1) v = Wr0[(size_t)k * 128 + r];
    else if (t == 2) v = Wl1[(size_t)k * 128 + r];
    else if (t == 3) v = Wr1[(size_t)k * 128 + r];
    else {
        if (r < 64) { if (r < OUT_DIM) v = Wl2[(size_t)k * OUT_DIM + r]; }
        else        { if (r - 64 < OUT_DIM) v = Wr2[(size_t)k * OUT_DIM + (r - 64)]; }
    }
    __nv_bfloat16 h, l;
    split_bf16(v, h, l);
    bh[i] = h; bl[i] = l;
}

// ---------------- WMMA GEMM (bf16x3 compensated) ----------------
// If X != null: load fp32 X tile and split to hi/lo in-kernel (layer 0).
// nphase==2: phase0 -> Gh fp16 (stride 128), phase1 -> Z fp32 (stride 128, direct)
// nphase==1: cols 0-63 -> Gh fp16 (stride 64), cols 64-127 -> Z fp32 (stride 64)
#define TILE_ELT (128 * SMA)
#define GEMM_SMEM_MAX ((2 + 4) * TILE_ELT * 2)

__global__ __launch_bounds__(256)
void gemm_wmma(const float* __restrict__ X,
               const __nv_bfloat16* __restrict__ Ah, const __nv_bfloat16* __restrict__ Al,
               const __nv_bfloat16* __restrict__ Bh, const __nv_bfloat16* __restrict__ Bl,
               int nphase, __half* __restrict__ Gh, float* __restrict__ Z, int M) {
    extern __shared__ __nv_bfloat16 sm[];
    __nv_bfloat16* sAh = sm;
    __nv_bfloat16* sAl = sm + TILE_ELT;
    const int tid = threadIdx.x;
    const int m0 = blockIdx.x * 128;

    if (X) {
        // fp32 tile -> split in-kernel
#pragma unroll
        for (int i = 0; i < 16; i++) {
            int u = i * 256 + tid;            // 0..4095 float4 units
            int row = u >> 5, c4 = (u & 31) * 4;
            float4 v = make_float4(0.f, 0.f, 0.f, 0.f);
            if (m0 + row < M)
                v = *(const float4*)(X + (size_t)(m0 + row) * 128 + c4);
            __nv_bfloat16 h[4], l[4];
            split_bf16(v.x, h[0], l[0]);
            split_bf16(v.y, h[1], l[1]);
            split_bf16(v.z, h[2], l[2]);
            split_bf16(v.w, h[3], l[3]);
            *(uint2*)(sAh + row * SMA + c4) = *(uint2*)h;
            *(uint2*)(sAl + row * SMA + c4) = *(uint2*)l;
        }
    } else {
#pragma unroll
        for (int i = 0; i < 8; i++) {
            int u = i * 256 + tid;
            int row = u >> 4, c8 = (u & 15) * 8;
            uint4 vh = make_uint4(0u, 0u, 0u, 0u), vl = vh;
            if (m0 + row < M) {
                vh = *(const uint4*)(Ah + (size_t)(m0 + row) * 128 + c8);
                vl = *(const uint4*)(Al + (size_t)(m0 + row) * 128 + c8);
            }
            *(uint4*)(sAh + row * SMA + c8) = vh;
            *(uint4*)(sAl + row * SMA + c8) = vl;
        }
    }
    for (int p = 0; p < nphase; p++) {
        __nv_bfloat16* dh = sm + (2 + 2 * p) * TILE_ELT;
        __nv_bfloat16* dl = dh + TILE_ELT;
        const __nv_bfloat16* gh = Bh + (size_t)p * 16384;
        const __nv_bfloat16* gl = Bl + (size_t)p * 16384;
#pragma unroll
        for (int i = 0; i < 8; i++) {
            int u = i * 256 + tid;
            int row = u >> 4, c8 = (u & 15) * 8;
            *(uint4*)(dh + row * SMA + c8) = *(const uint4*)(gh + row * 128 + c8);
            *(uint4*)(dl + row * SMA + c8) = *(const uint4*)(gl + row * 128 + c8);
        }
    }
    __syncthreads();

    const int wid = tid >> 5;
    const int wm = (wid & 3) * 32;
    const int wn = (wid >> 2) * 64;

    for (int p = 0; p < nphase; p++) {
        const __nv_bfloat16* sBh = sm + (2 + 2 * p) * TILE_ELT;
        const __nv_bfloat16* sBl = sBh + TILE_ELT;

        wmma::fragment<wmma::accumulator, 16, 16, 16, float> acc[2][4];
#pragma unroll
        for (int i = 0; i < 2; i++)
#pragma unroll
            for (int j = 0; j < 4; j++) wmma::fill_fragment(acc[i][j], 0.0f);

#pragma unroll
        for (int ks = 0; ks < 8; ks++) {
            wmma::fragment<wmma::matrix_a, 16, 16, 16, __nv_bfloat16, wmma::row_major> fah[2], fal[2];
            wmma::fragment<wmma::matrix_b, 16, 16, 16, __nv_bfloat16, wmma::col_major> fbh[4], fbl[4];
#pragma unroll
            for (int i = 0; i < 2; i++) {
                wmma::load_matrix_sync(fah[i], sAh + (wm + i * 16) * SMA + ks * 16, SMA);
                wmma::load_matrix_sync(fal[i], sAl + (wm + i * 16) * SMA + ks * 16, SMA);
            }
#pragma unroll
            for (int j = 0; j < 4; j++) {
                wmma::load_matrix_sync(fbh[j], sBh + (wn + j * 16) * SMA + ks * 16, SMA);
                wmma::load_matrix_sync(fbl[j], sBl + (wn + j * 16) * SMA + ks * 16, SMA);
            }
#pragma unroll
            for (int i = 0; i < 2; i++)
#pragma unroll
                for (int j = 0; j < 4; j++) {
                    wmma::mma_sync(acc[i][j], fah[i], fbh[j], acc[i][j]);
                    wmma::mma_sync(acc[i][j], fal[i], fbh[j], acc[i][j]);
                    wmma::mma_sync(acc[i][j], fah[i], fbl[j], acc[i][j]);
                }
        }

        if (p == 0) {
            float* stage = (float*)(sm + 2 * TILE_ELT);
            __syncthreads();
#pragma unroll
            for (int i = 0; i < 2; i++)
#pragma unroll
                for (int j = 0; j < 4; j++)
                    wmma::store_matrix_sync(stage + (wm + i * 16) * STG + wn + j * 16,
                                            acc[i][j], STG, wmma::mem_row_major);
            __syncthreads();

            if (nphase == 2) {
                for (int i = tid; i < 128 * 16; i += 256) {
                    int r = i >> 4, c8 = (i & 15) * 8;
                    if (m0 + r < M) {
                        __half h8[8];
#pragma unroll
                        for (int j = 0; j < 8; j++)
                            h8[j] = __float2half_rn(stage[r * STG + c8 + j]);
                        *(uint4*)(Gh + (size_t)(m0 + r) * 128 + c8) = *(uint4*)h8;
                    }
                }
            } else {
                for (int i = tid; i < 128 * 8; i += 256) {
                    int r = i >> 3, c8 = (i & 7) * 8;
                    if (m0 + r < M) {
                        __half h8[8];
#pragma unroll
                        for (int j = 0; j < 8; j++)
                            h8[j] = __float2half_rn(stage[r * STG + c8 + j]);
                        *(uint4*)(Gh + (size_t)(m0 + r) * 64 + c8) = *(uint4*)h8;
                    }
                }
                for (int i = tid; i < 128 * 16; i += 256) {
                    int r = i >> 4, c4 = (i & 15) * 4;
                    if (m0 + r < M)
                        *(float4*)(Z + (size_t)(m0 + r) * 64 + c4) =
                            *(float4*)(stage + r * STG + 64 + c4);
                }
            }
        } else {
#pragma unroll
            for (int i = 0; i < 2; i++)
#pragma unroll
                for (int j = 0; j < 4; j++)
                    wmma::store_matrix_sync(Z + (size_t)(m0 + wm + i * 16) * 128 + wn + j * 16,
                                            acc[i][j], 128, wmma::mem_row_major);
        }
    }
}

// ---------------- aggregation, warp per node (fp16 gather, 4-edge unroll) ----------
__device__ __forceinline__ void acc_row(float* a, uint2 u) {
    float2 p0 = __half22float2(*(const __half2*)&u.x);
    float2 p1 = __half22float2(*(const __half2*)&u.y);
    a[0] += p0.x; a[1] += p0.y; a[2] += p1.x; a[3] += p1.y;
}

__global__ void agg128_warp(const __half* __restrict__ G, const float* __restrict__ Z,
                            const float* __restrict__ bias,
                            __nv_bfloat16* __restrict__ oh, __nv_bfloat16* __restrict__ ol) {
    int w = (blockIdx.x * blockDim.x + threadIdx.x) >> 5;
    int lane = threadIdx.x & 31;
    if (w >= N_NODES) return;
    const int e0 = d_off[w], e1 = d_off[w + 1];
    const uint2* Gv = (const uint2*)G;
    float a0[4] = {0.f, 0.f, 0.f, 0.f};
    float a1[4] = {0.f, 0.f, 0.f, 0.f};
    float a2[4] = {0.f, 0.f, 0.f, 0.f};
    float a3[4] = {0.f, 0.f, 0.f, 0.f};
    int i = e0;
    for (; i + 4 <= e1; i += 4) {
        int s0 = __ldg(&d_esrc[i]);
        int s1 = __ldg(&d_esrc[i + 1]);
        int s2 = __ldg(&d_esrc[i + 2]);
        int s3 = __ldg(&d_esrc[i + 3]);
        uint2 u0 = __ldg(&Gv[(size_t)s0 * 32 + lane]);
        uint2 u1 = __ldg(&Gv[(size_t)s1 * 32 + lane]);
        uint2 u2 = __ldg(&Gv[(size_t)s2 * 32 + lane]);
        uint2 u3 = __ldg(&Gv[(size_t)s3 * 32 + lane]);
        acc_row(a0, u0); acc_row(a1, u1); acc_row(a2, u2); acc_row(a3, u3);
    }
    for (; i < e1; i++)
        acc_row(a0, __ldg(&Gv[(size_t)__ldg(&d_esrc[i]) * 32 + lane]));

    float inv = d_invd[w];
    float4 z = __ldg(&((const float4*)Z)[(size_t)w * 32 + lane]);
    float4 b = __ldg(&((const float4*)bias)[lane]);
    float o[4];
    o[0] = fmaxf(z.x + b.x + inv * ((a0[0] + a1[0]) + (a2[0] + a3[0])), 0.f);
    o[1] = fmaxf(z.y + b.y + inv * ((a0[1] + a1[1]) + (a2[1] + a3[1])), 0.f);
    o[2] = fmaxf(z.z + b.z + inv * ((a0[2] + a1[2]) + (a2[2] + a3[2])), 0.f);
    o[3] = fmaxf(z.w + b.w + inv * ((a0[3] + a1[3]) + (a2[3] + a3[3])), 0.f);

    __nv_bfloat16 hb[4], lb[4];
#pragma unroll
    for (int j = 0; j < 4; j++) split_bf16(o[j], hb[j], lb[j]);
    *(uint2*)&oh[(size_t)w * 128 + lane * 4] = *(uint2*)hb;
    *(uint2*)&ol[(size_t)w * 128 + lane * 4] = *(uint2*)lb;
}

// ---------------- layer-2 agg + log_softmax ----------------
// Gather rows are 64 fp16 (cols >= 47 zero). Half-warp per edge: lanes 0-15 edge i,
// lanes 16-31 edge i+1; each sub-lane owns 4 consecutive cols via one uint2 load.
__global__ void agg_lsm47_warp(const __half* __restrict__ G, const float* __restrict__ Z,
                               const float* __restrict__ bias, float* __restrict__ out) {
    int v = (blockIdx.x * blockDim.x + threadIdx.x) >> 5;
    int lane = threadIdx.x & 31;
    if (v >= N_NODES) return;
    const int e0 = d_off[v], e1 = d_off[v + 1];
    const int half = lane >> 4;       // which edge of the pair
    const int sub = lane & 15;        // column group: cols 4*sub .. 4*sub+3
    const uint2* Gv = (const uint2*)G;

    float a[4] = {0.f, 0.f, 0.f, 0.f};
    for (int i = e0 + half; i < e1; i += 2) {
        int s = __ldg(&d_esrc[i]);
        uint2 u = __ldg(&Gv[(size_t)s * 16 + sub]);
        acc_row(a, u);
    }
    // combine the two half-warps (lanes L and L+16 end with identical totals)
#pragma unroll
    for (int j = 0; j < 4; j++) a[j] += __shfl_xor_sync(0xFFFFFFFFu, a[j], 16);

    float inv = d_invd[v];
    float4 z = __ldg(&((const float4*)(Z + (size_t)v * 64))[sub]);
    float zz[4] = {z.x, z.y, z.z, z.w};
    float vals[4];
    float m = -INFINITY;
#pragma unroll
    for (int j = 0; j < 4; j++) {
        int c = 4 * sub + j;
        vals[j] = (c < OUT_DIM) ? (zz[j] + __ldg(&bias[c]) + inv * a[j]) : -INFINITY;
        m = fmaxf(m, vals[j]);
    }
#pragma unroll
    for (int o = 16; o > 0; o >>= 1) m = fmaxf(m, __shfl_xor_sync(0xFFFFFFFFu, m, o));
    float s = 0.f;
    if (half == 0) {
#pragma unroll
        for (int j = 0; j < 4; j++) {
            int c = 4 * sub + j;
            if (c < OUT_DIM) s += expf(vals[j] - m);
        }
    }
#pragma unroll
    for (int o = 16; o > 0; o >>= 1) s += __shfl_xor_sync(0xFFFFFFFFu, s, o);
    float l = m + logf(s);

    if (half == 0) {
        float* orow = out + (size_t)v * OUT_DIM;
#pragma unroll
        for (int j = 0; j < 4; j++) {
            int c = 4 * sub + j;
            if (c < OUT_DIM) orow[c] = vals[j] - l;
        }
    }
}

// ---------------- launch ----------------
extern "C" void kernel_launch(void* const* d_in, const int* in_sizes, int n_in,
                              void* d_out, int out_size) {
    const float* x   = (const float*)d_in[0];
    const int*   src = (const int*)d_in[1];
    const int*   dst = (const int*)d_in[2];
    const float* Wl0 = (const float*)d_in[3];
    const float* bl0 = (const float*)d_in[4];
    const float* Wr0 = (const float*)d_in[5];
    const float* Wl1 = (const float*)d_in[6];
    const float* bl1 = (const float*)d_in[7];
    const float* Wr1 = (const float*)d_in[8];
    const float* Wl2 = (const float*)d_in[9];
    const float* bl2 = (const float*)d_in[10];
    const float* Wr2 = (const float*)d_in[11];
    float* out = (float*)d_out;

    void *pGh, *pZ, *pAh, *pAl, *pBh, *pBl, *pCnt;
    cudaGetSymbolAddress(&pGh, d_Gh);
    cudaGetSymbolAddress(&pZ, d_Z);
    cudaGetSymbolAddress(&pAh, d_Ah);
    cudaGetSymbolAddress(&pAl, d_Al);
    cudaGetSymbolAddress(&pBh, d_Bh);
    cudaGetSymbolAddress(&pBl, d_Bl);
    cudaGetSymbolAddress(&pCnt, d_count);
    __half* Gh = (__half*)pGh;
    float* Z = (float*)pZ;
    __nv_bfloat16* Ah = (__nv_bfloat16*)pAh;
    __nv_bfloat16* Al = (__nv_bfloat16*)pAl;
    __nv_bfloat16* Bh = (__nv_bfloat16*)pBh;
    __nv_bfloat16* Bl = (__nv_bfloat16*)pBl;

    cudaFuncSetAttribute(gemm_wmma, cudaFuncAttributeMaxDynamicSharedMemorySize,
                         GEMM_SMEM_MAX);

    // CSR build
    cudaMemsetAsync(pCnt, 0, N_NODES * sizeof(int));
    count_kernel<<<(N_EDGES + 255) / 256, 256>>>(dst);
    scan_kernel<<<1, 1024>>>();
    scatter_kernel<<<(N_EDGES + 255) / 256, 256>>>(src, dst);

    wconv_all<<<(5 * 16384 + 255) / 256, 256>>>(Wl0, Wr0, Wl1, Wr1, Wl2, Wr2, Bh, Bl);

    const int gemm_grid = NPAD / 128;
    const int aggw_grid = (N_NODES * 32 + 255) / 256;
    const size_t smem2 = (size_t)(2 + 4) * TILE_ELT * 2;
    const size_t smem1 = (size_t)(2 + 2) * TILE_ELT * 2;

    // Layer 0 (reads fp32 x directly, splits in-kernel)
    gemm_wmma<<<gemm_grid, 256, smem2>>>(x, nullptr, nullptr, Bh, Bl, 2, Gh, Z, N_NODES);
    agg128_warp<<<aggw_grid, 256>>>(Gh, Z, bl0, Ah, Al);

    // Layer 1
    gemm_wmma<<<gemm_grid, 256, smem2>>>(nullptr, Ah, Al, Bh + 2 * 16384, Bl + 2 * 16384, 2, Gh, Z, N_NODES);
    agg128_warp<<<aggw_grid, 256>>>(Gh, Z, bl1, Ah, Al);

    // Layer 2
    gemm_wmma<<<gemm_grid, 256, smem1>>>(nullptr, Ah, Al, Bh + 4 * 16384, Bl + 4 * 16384, 1, Gh, Z, N_NODES);
    agg_lsm47_warp<<<aggw_grid, 256>>>(Gh, Z, bl2, out);
}